// round 8
// baseline (speedup 1.0000x reference)
#include <cuda_runtime.h>
#include <cstdint>

#define NQ     128
#define NK     2048
#define D5     768
#define SEQ    32
#define ZD     24
#define NTHR   256
#define KCHUNK 64
#define NB     8
#define NBATCH (KCHUNK / NB)

// per-buffer u64s: NB rows * 2 ksteps * 32 s * 4 j
#define BUF_U64 (NB * 2 * 32 * 4)          // 2048
#define SMEM_BYTES (2 * BUF_U64 * 8)       // 32768

// bf16(16.0) in lo half of a bf16x2 word -> B bias column 24
#define BIASPK 0x00004180u

typedef unsigned long long ull;

__device__ __forceinline__ uint32_t pk(float lo, float hi) {
    uint32_t r; asm("cvt.rn.bf16x2.f32 %0, %1, %2;" : "=r"(r) : "f"(hi), "f"(lo));
    return r;
}

__device__ __forceinline__ void mma16_z(float* c, const uint32_t* a, ull b) {
    uint32_t b0 = (uint32_t)b, b1 = (uint32_t)(b >> 32);
    asm volatile(
        "mma.sync.aligned.m16n8k16.row.col.f32.bf16.bf16.f32 "
        "{%0,%1,%2,%3}, {%4,%5,%6,%7}, {%8,%9}, {%10,%10,%10,%10};"
        : "=f"(c[0]), "=f"(c[1]), "=f"(c[2]), "=f"(c[3])
        : "r"(a[0]), "r"(a[1]), "r"(a[2]), "r"(a[3]), "r"(b0), "r"(b1), "f"(0.0f));
}
__device__ __forceinline__ void mma16(float* c, const uint32_t* a, ull b) {
    uint32_t b0 = (uint32_t)b, b1 = (uint32_t)(b >> 32);
    asm volatile(
        "mma.sync.aligned.m16n8k16.row.col.f32.bf16.bf16.f32 "
        "{%0,%1,%2,%3}, {%4,%5,%6,%7}, {%8,%9}, {%0,%1,%2,%3};"
        : "+f"(c[0]), "+f"(c[1]), "+f"(c[2]), "+f"(c[3])
        : "r"(a[0]), "r"(a[1]), "r"(a[2]), "r"(a[3]), "r"(b0), "r"(b1));
}

// Stage NB memory rows as bf16, zipped so each B fragment is one LDS.64.
// ks=1 hi words hold B cols 24..31: col 24 = 16.0 (bias), rest 0.
__device__ __forceinline__ void stage(ull* __restrict__ buf,
                                      const float* __restrict__ kbase, int tid) {
    int kk = tid >> 5, s = tid & 31;
    const float4* p = reinterpret_cast<const float4*>(kbase + kk * D5 + s * ZD);
    float4 x0 = p[0], x1 = p[1], x2 = p[2], x3 = p[3], x4 = p[4], x5 = p[5];
    uint32_t p0 = pk(x0.x, x0.y), p1 = pk(x0.z, x0.w);
    uint32_t p2 = pk(x1.x, x1.y), p3 = pk(x1.z, x1.w);
    uint32_t p4 = pk(x2.x, x2.y), p5 = pk(x2.z, x2.w);
    uint32_t p6 = pk(x3.x, x3.y), p7 = pk(x3.z, x3.w);
    uint32_t p8 = pk(x4.x, x4.y), p9 = pk(x4.z, x4.w);
    uint32_t pA = pk(x5.x, x5.y), pB = pk(x5.z, x5.w);
    ulonglong2* d0 = reinterpret_cast<ulonglong2*>(buf + ((size_t)(kk * 2) * 32 + s) * 4);
    d0[0] = make_ulonglong2((ull)p0 | ((ull)p4 << 32), (ull)p1 | ((ull)p5 << 32));
    d0[1] = make_ulonglong2((ull)p2 | ((ull)p6 << 32), (ull)p3 | ((ull)p7 << 32));
    ulonglong2* d1 = reinterpret_cast<ulonglong2*>(buf + ((size_t)(kk * 2 + 1) * 32 + s) * 4);
    d1[0] = make_ulonglong2((ull)p8 | ((ull)BIASPK << 32), (ull)p9);
    d1[1] = make_ulonglong2((ull)pA, (ull)pB);
}

extern __shared__ ull sbuf[];

__global__ __launch_bounds__(NTHR, 3)
void matcher_hmma(const float* __restrict__ tgt,
                  const float* __restrict__ mem,
                  float* __restrict__ out)
{
    const int tid  = threadIdx.x;
    const int warp = tid >> 5;
    const int lane = tid & 31;
    const int gr   = lane >> 2;
    const int gc   = lane & 3;

    const int q0 = (blockIdx.x >> 5) * 8;       // 16 q-chunks
    const int k0 = (blockIdx.x & 31) * KCHUNK;  // 32 k-chunks
    const int q  = q0 + warp;

    // A fragments (bf16 pairs), resident: [mi][ks][4].
    // ks=1 slots 2,3 are A cols 24+2gc,25+2gc: bias col 24 = 16.0 lives at gc==0.
    uint32_t afr[2][2][4];
    {
        const float* a = tgt + (size_t)q * D5;
        const uint32_t abias = (gc == 0) ? BIASPK : 0u;
        #pragma unroll
        for (int mi = 0; mi < 2; ++mi) {
            int r = gr + 16 * mi;
            const float* r0 = a + r * ZD;
            const float* r1 = a + (r + 8) * ZD;
            afr[mi][0][0] = pk(r0[2 * gc],      r0[2 * gc + 1]);
            afr[mi][0][1] = pk(r1[2 * gc],      r1[2 * gc + 1]);
            afr[mi][0][2] = pk(r0[2 * gc + 8],  r0[2 * gc + 9]);
            afr[mi][0][3] = pk(r1[2 * gc + 8],  r1[2 * gc + 9]);
            afr[mi][1][0] = pk(r0[2 * gc + 16], r0[2 * gc + 17]);
            afr[mi][1][1] = pk(r1[2 * gc + 16], r1[2 * gc + 17]);
            afr[mi][1][2] = abias;
            afr[mi][1][3] = abias;
        }
    }

    float* __restrict__ out0 = out + (size_t)q * NK;
    float* __restrict__ out1 = out0 + (size_t)NQ * NK;

    stage(sbuf, mem + (size_t)k0 * D5, tid);
    __syncthreads();

    const unsigned rowmask = 0xFu << (lane & ~3);        // 4-lane gc group (same gr)
    const unsigned colmask = 0x11111111u << gc;          // 8-lane gr group (same gc)

    for (int b = 0; b < NBATCH; ++b) {
        ull* __restrict__ cur = sbuf + (size_t)(b & 1) * BUF_U64;
        if (b + 1 < NBATCH)
            stage(sbuf + (size_t)((b + 1) & 1) * BUF_U64,
                  mem + (size_t)(k0 + (b + 1) * NB) * D5, tid);

        float part[NB];

        #pragma unroll 1
        for (int kk = 0; kk < NB; ++kk) {
            const ull* __restrict__ bb = cur + (size_t)kk * 256;
            ull bf0[4], bf1[4];
            #pragma unroll
            for (int ni = 0; ni < 4; ++ni) {
                bf0[ni] = bb[(gr + 8 * ni) * 4 + gc];
                bf1[ni] = bb[(32 + gr + 8 * ni) * 4 + gc];
            }
            float acc[2][4][4];
            #pragma unroll
            for (int mi = 0; mi < 2; ++mi)
                #pragma unroll
                for (int ni = 0; ni < 4; ++ni) {
                    mma16_z(acc[mi][ni], afr[mi][0], bf0[ni]);
                    mma16(acc[mi][ni], afr[mi][1], bf1[ni]);
                }

            // In-thread row maxes (4 slots: rows gr+8h+16mi, over 8 cols)
            float rsum = 0.f;
            #pragma unroll
            for (int mi = 0; mi < 2; ++mi)
                #pragma unroll
                for (int h = 0; h < 2; ++h) {
                    float m = fmaxf(acc[mi][0][2 * h], acc[mi][0][2 * h + 1]);
                    #pragma unroll
                    for (int ni = 1; ni < 4; ++ni)
                        m = fmaxf(m, fmaxf(acc[mi][ni][2 * h], acc[mi][ni][2 * h + 1]));
                    // biased positive -> u32 max == float max; 1 REDUX over gc group
                    rsum += __uint_as_float(
                        __reduce_max_sync(rowmask, __float_as_uint(m)));
                }

            // In-thread col maxes (8 slots: cols 8ni+2gc+p, over 4 rows)
            float csum = 0.f;
            #pragma unroll
            for (int ni = 0; ni < 4; ++ni)
                #pragma unroll
                for (int p = 0; p < 2; ++p) {
                    float m = fmaxf(fmaxf(acc[0][ni][p], acc[0][ni][p + 2]),
                                    fmaxf(acc[1][ni][p], acc[1][ni][p + 2]));
                    csum += __uint_as_float(
                        __reduce_max_sync(colmask, __float_as_uint(m)));
                }

            // row maxes replicated 4x across warp, col maxes 8x
            part[kk] = rsum * 0.25f + csum * 0.125f;
        }

        // ---- Batched warp-sum of 8 partials via value-splitting reduction ----
        float t4[4];
        {
            bool hi = (lane & 1);
            #pragma unroll
            for (int j = 0; j < 4; ++j) {
                float send = hi ? part[j] : part[j + 4];
                float keep = hi ? part[j + 4] : part[j];
                t4[j] = keep + __shfl_xor_sync(0xffffffffu, send, 1);
            }
        }
        float t2[2];
        {
            bool hi = (lane & 2);
            #pragma unroll
            for (int j = 0; j < 2; ++j) {
                float send = hi ? t4[j] : t4[j + 2];
                float keep = hi ? t4[j + 2] : t4[j];
                t2[j] = keep + __shfl_xor_sync(0xffffffffu, send, 2);
            }
        }
        float v;
        {
            bool hi = (lane & 4);
            float send = hi ? t2[0] : t2[1];
            float keep = hi ? t2[1] : t2[0];
            v = keep + __shfl_xor_sync(0xffffffffu, send, 4);
        }
        v += __shfl_xor_sync(0xffffffffu, v, 8);
        v += __shfl_xor_sync(0xffffffffu, v, 16);

        // lane (0..7) owns partial index j = 4*bit0 + 2*bit1 + bit2
        if (lane < 8) {
            int j = ((lane & 1) << 2) | (lane & 2) | ((lane >> 2) & 1);
            // mean = v/64 - 256 ; sigmoid(mean) = 1/(1+exp(256 - v/64))
            float res = 1.0f / (1.0f + __expf(256.0f - v * 0.015625f));
            int k = k0 + b * NB + j;
            out0[k] = res;
            out1[k] = res;
        }
        __syncthreads();
    }
}

extern "C" void kernel_launch(void* const* d_in, const int* in_sizes, int n_in,
                              void* d_out, int out_size)
{
    const float* tgt = (const float*)d_in[0];   // [128, 768]
    const float* mem = (const float*)d_in[1];   // [2048, 768]
    float* out = (float*)d_out;                 // [2, 128, 2048]
    (void)in_sizes; (void)n_in; (void)out_size;

    cudaFuncSetAttribute(matcher_hmma,
                         cudaFuncAttributeMaxDynamicSharedMemorySize, SMEM_BYTES);
    matcher_hmma<<<512, NTHR, SMEM_BYTES>>>(tgt, mem, out);
}

// round 9
// speedup vs baseline: 5.8495x; 5.8495x over previous
#include <cuda_runtime.h>
#include <cstdint>

#define NQ     128
#define NK     2048
#define D5     768
#define SEQ    32
#define ZD     24
#define NTHR   256
#define KCHUNK 32
#define NB     8
#define NBATCH (KCHUNK / NB)

// per-buffer u64s: NB rows * 2 ksteps * 32 s * 4 j
#define BUF_U64 (NB * 2 * 32 * 4)          // 2048
#define SMEM_BYTES (2 * BUF_U64 * 8)       // 32768

typedef unsigned long long ull;

__device__ __forceinline__ uint32_t pk(float lo, float hi) {
    uint32_t r; asm("cvt.rn.bf16x2.f32 %0, %1, %2;" : "=r"(r) : "f"(hi), "f"(lo));
    return r;
}

__device__ __forceinline__ void mma16_z(float* c, const uint32_t* a, ull b) {
    uint32_t b0 = (uint32_t)b, b1 = (uint32_t)(b >> 32);
    asm volatile(
        "mma.sync.aligned.m16n8k16.row.col.f32.bf16.bf16.f32 "
        "{%0,%1,%2,%3}, {%4,%5,%6,%7}, {%8,%9}, {%10,%10,%10,%10};"
        : "=f"(c[0]), "=f"(c[1]), "=f"(c[2]), "=f"(c[3])
        : "r"(a[0]), "r"(a[1]), "r"(a[2]), "r"(a[3]), "r"(b0), "r"(b1), "f"(0.0f));
}
__device__ __forceinline__ void mma16(float* c, const uint32_t* a, ull b) {
    uint32_t b0 = (uint32_t)b, b1 = (uint32_t)(b >> 32);
    asm volatile(
        "mma.sync.aligned.m16n8k16.row.col.f32.bf16.bf16.f32 "
        "{%0,%1,%2,%3}, {%4,%5,%6,%7}, {%8,%9}, {%0,%1,%2,%3};"
        : "+f"(c[0]), "+f"(c[1]), "+f"(c[2]), "+f"(c[3])
        : "r"(a[0]), "r"(a[1]), "r"(a[2]), "r"(a[3]), "r"(b0), "r"(b1));
}

// Stage NB memory rows as bf16, zipped so each B fragment is one LDS.64.
__device__ __forceinline__ void stage(ull* __restrict__ buf,
                                      const float* __restrict__ kbase, int tid) {
    int kk = tid >> 5, s = tid & 31;
    const float4* p = reinterpret_cast<const float4*>(kbase + kk * D5 + s * ZD);
    float4 x0 = p[0], x1 = p[1], x2 = p[2], x3 = p[3], x4 = p[4], x5 = p[5];
    uint32_t p0 = pk(x0.x, x0.y), p1 = pk(x0.z, x0.w);
    uint32_t p2 = pk(x1.x, x1.y), p3 = pk(x1.z, x1.w);
    uint32_t p4 = pk(x2.x, x2.y), p5 = pk(x2.z, x2.w);
    uint32_t p6 = pk(x3.x, x3.y), p7 = pk(x3.z, x3.w);
    uint32_t p8 = pk(x4.x, x4.y), p9 = pk(x4.z, x4.w);
    uint32_t pA = pk(x5.x, x5.y), pB = pk(x5.z, x5.w);
    ulonglong2* d0 = reinterpret_cast<ulonglong2*>(buf + ((size_t)(kk * 2) * 32 + s) * 4);
    d0[0] = make_ulonglong2((ull)p0 | ((ull)p4 << 32), (ull)p1 | ((ull)p5 << 32));
    d0[1] = make_ulonglong2((ull)p2 | ((ull)p6 << 32), (ull)p3 | ((ull)p7 << 32));
    ulonglong2* d1 = reinterpret_cast<ulonglong2*>(buf + ((size_t)(kk * 2 + 1) * 32 + s) * 4);
    d1[0] = make_ulonglong2((ull)p8, (ull)p9);
    d1[1] = make_ulonglong2((ull)pA, (ull)pB);
}

extern __shared__ ull sbuf[];

__global__ __launch_bounds__(NTHR, 3)
void matcher_hmma(const float* __restrict__ tgt,
                  const float* __restrict__ mem,
                  float* __restrict__ out)
{
    const int tid  = threadIdx.x;
    const int warp = tid >> 5;
    const int lane = tid & 31;
    const int gr   = lane >> 2;
    const int gc   = lane & 3;

    const int q0 = (blockIdx.x >> 6) * 8;       // 16 q-chunks
    const int k0 = (blockIdx.x & 63) * KCHUNK;  // 64 k-chunks
    const int q  = q0 + warp;

    // A fragments (bf16 pairs), resident: [mi][ks][4]
    uint32_t afr[2][2][4];
    {
        const float* a = tgt + (size_t)q * D5;
        #pragma unroll
        for (int mi = 0; mi < 2; ++mi) {
            int r = gr + 16 * mi;
            const float* r0 = a + r * ZD;
            const float* r1 = a + (r + 8) * ZD;
            afr[mi][0][0] = pk(r0[2 * gc],      r0[2 * gc + 1]);
            afr[mi][0][1] = pk(r1[2 * gc],      r1[2 * gc + 1]);
            afr[mi][0][2] = pk(r0[2 * gc + 8],  r0[2 * gc + 9]);
            afr[mi][0][3] = pk(r1[2 * gc + 8],  r1[2 * gc + 9]);
            afr[mi][1][0] = pk(r0[2 * gc + 16], r0[2 * gc + 17]);
            afr[mi][1][1] = pk(r1[2 * gc + 16], r1[2 * gc + 17]);
            afr[mi][1][2] = 0u;
            afr[mi][1][3] = 0u;
        }
    }

    float* __restrict__ out0 = out + (size_t)q * NK;
    float* __restrict__ out1 = out0 + (size_t)NQ * NK;

    stage(sbuf, mem + (size_t)k0 * D5, tid);
    __syncthreads();

    const int p0b = (lane >> 2) & 1;
    const int p1b = (lane >> 3) & 1;
    const int p2b = (lane >> 4) & 1;
    const int q0b = lane & 1;
    const int q1b = (lane >> 1) & 1;

    for (int b = 0; b < NBATCH; ++b) {
        ull* __restrict__ cur = sbuf + (size_t)(b & 1) * BUF_U64;
        if (b + 1 < NBATCH)
            stage(sbuf + (size_t)((b + 1) & 1) * BUF_U64,
                  mem + (size_t)(k0 + (b + 1) * NB) * D5, tid);

        float part[NB];

        #pragma unroll 1
        for (int kk = 0; kk < NB; ++kk) {
            const ull* __restrict__ bb = cur + (size_t)kk * 256;
            ull bf0[4], bf1[4];
            #pragma unroll
            for (int ni = 0; ni < 4; ++ni) {
                bf0[ni] = bb[(gr + 8 * ni) * 4 + gc];
                bf1[ni] = bb[(32 + gr + 8 * ni) * 4 + gc];
            }
            float acc[2][4][4];
            #pragma unroll
            for (int mi = 0; mi < 2; ++mi)
                #pragma unroll
                for (int ni = 0; ni < 4; ++ni) {
                    mma16_z(acc[mi][ni], afr[mi][0], bf0[ni]);
                    mma16(acc[mi][ni], afr[mi][1], bf1[ni]);
                }

            // ---- In-thread row maxes (4 slots), col maxes (8 slots) ----
            float rm[4];
            #pragma unroll
            for (int mi = 0; mi < 2; ++mi)
                #pragma unroll
                for (int h = 0; h < 2; ++h) {
                    float m = fmaxf(acc[mi][0][2 * h], acc[mi][0][2 * h + 1]);
                    #pragma unroll
                    for (int ni = 1; ni < 4; ++ni)
                        m = fmaxf(m, fmaxf(acc[mi][ni][2 * h], acc[mi][ni][2 * h + 1]));
                    rm[2 * mi + h] = m;
                }
            float cm[8];
            #pragma unroll
            for (int ni = 0; ni < 4; ++ni)
                #pragma unroll
                for (int p = 0; p < 2; ++p)
                    cm[ni * 2 + p] = fmaxf(fmaxf(acc[0][ni][p], acc[0][ni][p + 2]),
                                           fmaxf(acc[1][ni][p], acc[1][ni][p + 2]));

            // ---- Reduce-scatter: rows over gc bits (xor 1,2) ----
            float row_own;
            {
                float s0 = q0b ? rm[0] : rm[2], k0v = q0b ? rm[2] : rm[0];
                float s1 = q0b ? rm[1] : rm[3], k1v = q0b ? rm[3] : rm[1];
                float w0 = fmaxf(k0v, __shfl_xor_sync(0xffffffffu, s0, 1));
                float w1 = fmaxf(k1v, __shfl_xor_sync(0xffffffffu, s1, 1));
                float s2 = q1b ? w0 : w1, k2v = q1b ? w1 : w0;
                row_own = fmaxf(k2v, __shfl_xor_sync(0xffffffffu, s2, 2));
            }
            // ---- Reduce-scatter: cols over gr bits (xor 4,8,16) ----
            float col_own;
            {
                float v4[4];
                #pragma unroll
                for (int j = 0; j < 4; ++j) {
                    float s = p0b ? cm[j] : cm[j + 4];
                    float k = p0b ? cm[j + 4] : cm[j];
                    v4[j] = fmaxf(k, __shfl_xor_sync(0xffffffffu, s, 4));
                }
                float v2[2];
                #pragma unroll
                for (int j = 0; j < 2; ++j) {
                    float s = p1b ? v4[j] : v4[j + 2];
                    float k = p1b ? v4[j + 2] : v4[j];
                    v2[j] = fmaxf(k, __shfl_xor_sync(0xffffffffu, s, 8));
                }
                float s = p2b ? v2[0] : v2[1];
                float k = p2b ? v2[1] : v2[0];
                col_own = fmaxf(k, __shfl_xor_sync(0xffffffffu, s, 16));
            }

            part[kk] = row_own + col_own;   // each lane owns 1 row + 1 col
        }

        // ---- Batched warp-sum of 8 partials (value-splitting reduction) ----
        float t4[4];
        {
            bool hi = (lane & 1);
            #pragma unroll
            for (int j = 0; j < 4; ++j) {
                float send = hi ? part[j] : part[j + 4];
                float keep = hi ? part[j + 4] : part[j];
                t4[j] = keep + __shfl_xor_sync(0xffffffffu, send, 1);
            }
        }
        float t2[2];
        {
            bool hi = (lane & 2);
            #pragma unroll
            for (int j = 0; j < 2; ++j) {
                float send = hi ? t4[j] : t4[j + 2];
                float keep = hi ? t4[j + 2] : t4[j];
                t2[j] = keep + __shfl_xor_sync(0xffffffffu, send, 2);
            }
        }
        float v;
        {
            bool hi = (lane & 4);
            float send = hi ? t2[0] : t2[1];
            float keep = hi ? t2[1] : t2[0];
            v = keep + __shfl_xor_sync(0xffffffffu, send, 4);
        }
        v += __shfl_xor_sync(0xffffffffu, v, 8);
        v += __shfl_xor_sync(0xffffffffu, v, 16);

        // lane (0..7) owns partial index j = 4*bit0 + 2*bit1 + bit2
        if (lane < 8) {
            int j = ((lane & 1) << 2) | (lane & 2) | ((lane >> 2) & 1);
            float res = 1.0f / (1.0f + __expf(v * -0.015625f));
            int k = k0 + b * NB + j;
            out0[k] = res;
            out1[k] = res;
        }
        __syncthreads();
    }
}

extern "C" void kernel_launch(void* const* d_in, const int* in_sizes, int n_in,
                              void* d_out, int out_size)
{
    const float* tgt = (const float*)d_in[0];   // [128, 768]
    const float* mem = (const float*)d_in[1];   // [2048, 768]
    float* out = (float*)d_out;                 // [2, 128, 2048]
    (void)in_sizes; (void)n_in; (void)out_size;

    cudaFuncSetAttribute(matcher_hmma,
                         cudaFuncAttributeMaxDynamicSharedMemorySize, SMEM_BYTES);
    matcher_hmma<<<1024, NTHR, SMEM_BYTES>>>(tgt, mem, out);
}